// round 2
// baseline (speedup 1.0000x reference)
#include <cuda_runtime.h>
#include <math.h>

#define NNODES 50000
#define NEDGES 1600000
#define INCH   128
#define HEADS  4
#define HDIM   32
#define OUTC   128
#define NEG_SLOPE 0.2f

// Scratch (static device globals; no allocation allowed)
__device__ float g_h[NNODES * OUTC];              // projected features [N,128]
__device__ float g_as[NNODES * HEADS];            // a_src [N,4]
__device__ float g_ad[NNODES * HEADS];            // a_dst [N,4]
__device__ float g_amax[NNODES * HEADS];          // segment max [N,4]
__device__ float g_den[NNODES * HEADS];           // segment denom [N,4]
__device__ float g_ew[(NEDGES + NNODES) * HEADS]; // exp weights per edge [ET,4]

__device__ __forceinline__ void atomicMaxFloat(float* addr, float val) {
    // standard two-sided trick; addr must be initialized to -inf
    if (val >= 0.0f) {
        atomicMax((int*)addr, __float_as_int(val));
    } else {
        atomicMin((unsigned int*)addr, __float_as_uint(val));
    }
}

__device__ __forceinline__ float leaky(float v) {
    return v > 0.0f ? v : NEG_SLOPE * v;
}

// ---------------------------------------------------------------------------
// Init: zero out accumulator, amax=-inf, den=0
// ---------------------------------------------------------------------------
__global__ void k_init(float* __restrict__ out, int N) {
    int i = blockIdx.x * blockDim.x + threadIdx.x;
    int total = N * OUTC;
    if (i < total) out[i] = 0.0f;
    if (i < N * HEADS) {
        g_amax[i] = -__int_as_float(0x7f800000); // -inf
        g_den[i] = 0.0f;
    }
}

// ---------------------------------------------------------------------------
// Projection + per-node attention logits. One block = one node, 128 threads.
// ---------------------------------------------------------------------------
__global__ void k_proj(const float* __restrict__ x, const float* __restrict__ W,
                       const float* __restrict__ att_s, const float* __restrict__ att_d,
                       int N) {
    int n = blockIdx.x;
    if (n >= N) return;
    int t = threadIdx.x; // 0..127 -> output column; head = t>>5
    __shared__ float xs[INCH];
    xs[t] = x[n * INCH + t];
    __syncthreads();

    float acc = 0.0f;
#pragma unroll 16
    for (int k = 0; k < INCH; k++) {
        acc = fmaf(xs[k], __ldg(&W[k * OUTC + t]), acc);
    }
    g_h[n * OUTC + t] = acc;

    // warp (= head) reductions for attention logits
    float vs = acc * __ldg(&att_s[t]);
    float vd = acc * __ldg(&att_d[t]);
#pragma unroll
    for (int o = 16; o > 0; o >>= 1) {
        vs += __shfl_down_sync(0xffffffffu, vs, o);
        vd += __shfl_down_sync(0xffffffffu, vd, o);
    }
    if ((t & 31) == 0) {
        int h = t >> 5;
        g_as[n * HEADS + h] = vs;
        g_ad[n * HEADS + h] = vd;
    }
}

// ---------------------------------------------------------------------------
// Pass A: segment max of leaky_relu(a_src[s]+a_dst[d]) over dst
// edge_index is int32 (JAX silently downcasts int64 without x64 enabled)
// ---------------------------------------------------------------------------
__global__ void k_max(const int* __restrict__ ei, int E, int N) {
    int e = blockIdx.x * blockDim.x + threadIdx.x;
    int ET = E + N;
    if (e >= ET) return;
    int s, d;
    if (e < E) {
        s = ei[e];
        d = ei[E + e];
    } else {
        s = d = e - E;
    }
    float4 as = *(const float4*)&g_as[s * HEADS];
    float4 ad = *(const float4*)&g_ad[d * HEADS];
    float l0 = leaky(as.x + ad.x);
    float l1 = leaky(as.y + ad.y);
    float l2 = leaky(as.z + ad.z);
    float l3 = leaky(as.w + ad.w);
    atomicMaxFloat(&g_amax[d * HEADS + 0], l0);
    atomicMaxFloat(&g_amax[d * HEADS + 1], l1);
    atomicMaxFloat(&g_amax[d * HEADS + 2], l2);
    atomicMaxFloat(&g_amax[d * HEADS + 3], l3);
}

// ---------------------------------------------------------------------------
// Pass B: exp(alpha - amax[d]) -> stored per edge; atomicAdd into denom
// ---------------------------------------------------------------------------
__global__ void k_exp(const int* __restrict__ ei, int E, int N) {
    int e = blockIdx.x * blockDim.x + threadIdx.x;
    int ET = E + N;
    if (e >= ET) return;
    int s, d;
    if (e < E) {
        s = ei[e];
        d = ei[E + e];
    } else {
        s = d = e - E;
    }
    float4 as = *(const float4*)&g_as[s * HEADS];
    float4 ad = *(const float4*)&g_ad[d * HEADS];
    float4 mx = *(const float4*)&g_amax[d * HEADS];
    float4 w;
    w.x = __expf(leaky(as.x + ad.x) - mx.x);
    w.y = __expf(leaky(as.y + ad.y) - mx.y);
    w.z = __expf(leaky(as.z + ad.z) - mx.z);
    w.w = __expf(leaky(as.w + ad.w) - mx.w);
    *(float4*)&g_ew[e * HEADS] = w;
    atomicAdd(&g_den[d * HEADS + 0], w.x);
    atomicAdd(&g_den[d * HEADS + 1], w.y);
    atomicAdd(&g_den[d * HEADS + 2], w.z);
    atomicAdd(&g_den[d * HEADS + 3], w.w);
}

// ---------------------------------------------------------------------------
// Pass C: weighted scatter-aggregate. One warp per edge; lane handles
// columns lane+32*i (head i). Coalesced gather of h[src], coalesced
// atomicAdd into out[dst].
// ---------------------------------------------------------------------------
__global__ void k_agg(const int* __restrict__ ei, float* __restrict__ out,
                      int E, int N) {
    int warp = (int)((blockIdx.x * (long long)blockDim.x + threadIdx.x) >> 5);
    int lane = threadIdx.x & 31;
    int ET = E + N;
    if (warp >= ET) return;
    int s = 0, d = 0;
    if (lane == 0) {
        if (warp < E) {
            s = ei[warp];
            d = ei[E + warp];
        } else {
            s = d = warp - E;
        }
    }
    s = __shfl_sync(0xffffffffu, s, 0);
    d = __shfl_sync(0xffffffffu, d, 0);

    const float* hs = &g_h[(long long)s * OUTC];
    float* od = &out[(long long)d * OUTC];
    const float* ew = &g_ew[warp * HEADS];
    const float* den = &g_den[d * HEADS];

#pragma unroll
    for (int i = 0; i < HEADS; i++) {
        float wt = ew[i] / (den[i] + 1e-16f);
        int c = i * 32 + lane;
        atomicAdd(&od[c], wt * hs[c]);
    }
}

// ---------------------------------------------------------------------------
// Epilogue: out = elu(out + bias)
// ---------------------------------------------------------------------------
__global__ void k_final(float* __restrict__ out, const float* __restrict__ bias, int N) {
    int i = blockIdx.x * blockDim.x + threadIdx.x;
    if (i >= N * OUTC) return;
    float v = out[i] + __ldg(&bias[i & (OUTC - 1)]);
    out[i] = v > 0.0f ? v : expm1f(v);
}

// ---------------------------------------------------------------------------
extern "C" void kernel_launch(void* const* d_in, const int* in_sizes, int n_in,
                              void* d_out, int out_size) {
    const float* x = (const float*)d_in[0];
    const int* ei = (const int*)d_in[1];   // int32: jax downcasts int64 w/o x64
    const float* W = (const float*)d_in[2];
    const float* att_s = (const float*)d_in[3];
    const float* att_d = (const float*)d_in[4];
    const float* bias = (const float*)d_in[5];
    float* out = (float*)d_out;

    int N = in_sizes[0] / INCH;
    int E = in_sizes[1] / 2;
    if (N > NNODES) N = NNODES;
    if (E > NEDGES) E = NEDGES;
    int ET = E + N;

    {
        int total = N * OUTC;
        k_init<<<(total + 255) / 256, 256>>>(out, N);
    }
    k_proj<<<N, 128>>>(x, W, att_s, att_d, N);
    k_max<<<(ET + 255) / 256, 256>>>(ei, E, N);
    k_exp<<<(ET + 255) / 256, 256>>>(ei, E, N);
    {
        long long threads = (long long)ET * 32;
        int blocks = (int)((threads + 255) / 256);
        k_agg<<<blocks, 256>>>(ei, out, E, N);
    }
    k_final<<<(N * OUTC + 255) / 256, 256>>>(out, bias, N);
}

// round 3
// speedup vs baseline: 1.5839x; 1.5839x over previous
#include <cuda_runtime.h>
#include <math.h>

#define NNODES 50000
#define NEDGES 1600000
#define INCH   128
#define HEADS  4
#define OUTC   128
#define NEG_SLOPE 0.2f
#define CHUNK  128

// Scratch (static device globals; no allocation allowed)
__device__ float g_h[NNODES * OUTC];          // projected features [N,128]
__device__ float g_as[NNODES * HEADS];        // a_src [N,4]
__device__ float g_ad[NNODES * HEADS];        // a_dst [N,4]
__device__ int   g_cnt[NNODES];               // in-degree (w/o self loop)
__device__ int   g_off[NNODES];               // CSR offsets (exclusive scan)
__device__ int   g_cur[NNODES];               // scatter cursors
__device__ int   g_csr_src[NEDGES];           // src node per CSR slot

__device__ __forceinline__ float leaky(float v) {
    return v > 0.0f ? v : NEG_SLOPE * v;
}
__device__ __forceinline__ float4 leaky4(float4 a, float4 b) {
    float4 r;
    r.x = leaky(a.x + b.x); r.y = leaky(a.y + b.y);
    r.z = leaky(a.z + b.z); r.w = leaky(a.w + b.w);
    return r;
}
__device__ __forceinline__ float4 max4(float4 a, float4 b) {
    float4 r;
    r.x = fmaxf(a.x, b.x); r.y = fmaxf(a.y, b.y);
    r.z = fmaxf(a.z, b.z); r.w = fmaxf(a.w, b.w);
    return r;
}
__device__ __forceinline__ float4 exp4(float4 l, float4 m) {
    float4 r;
    r.x = __expf(l.x - m.x); r.y = __expf(l.y - m.y);
    r.z = __expf(l.z - m.z); r.w = __expf(l.w - m.w);
    return r;
}
__device__ __forceinline__ float sel4(float4 v, int h) {
    return h == 0 ? v.x : h == 1 ? v.y : h == 2 ? v.z : v.w;
}

// ---------------------------------------------------------------------------
// Zero counters/cursors
// ---------------------------------------------------------------------------
__global__ void k_zero(int N) {
    int i = blockIdx.x * blockDim.x + threadIdx.x;
    if (i < N) { g_cnt[i] = 0; g_cur[i] = 0; }
}

// ---------------------------------------------------------------------------
// Projection + per-node attention logits. One block = one node, 128 threads.
// ---------------------------------------------------------------------------
__global__ void k_proj(const float* __restrict__ x, const float* __restrict__ W,
                       const float* __restrict__ att_s, const float* __restrict__ att_d,
                       int N) {
    int n = blockIdx.x;
    if (n >= N) return;
    int t = threadIdx.x;
    __shared__ float xs[INCH];
    xs[t] = x[n * INCH + t];
    __syncthreads();

    float acc = 0.0f;
#pragma unroll 16
    for (int k = 0; k < INCH; k++)
        acc = fmaf(xs[k], __ldg(&W[k * OUTC + t]), acc);
    g_h[n * OUTC + t] = acc;

    float vs = acc * __ldg(&att_s[t]);
    float vd = acc * __ldg(&att_d[t]);
#pragma unroll
    for (int o = 16; o > 0; o >>= 1) {
        vs += __shfl_down_sync(0xffffffffu, vs, o);
        vd += __shfl_down_sync(0xffffffffu, vd, o);
    }
    if ((t & 31) == 0) {
        int h = t >> 5;
        g_as[n * HEADS + h] = vs;
        g_ad[n * HEADS + h] = vd;
    }
}

// ---------------------------------------------------------------------------
// Histogram of destination nodes
// ---------------------------------------------------------------------------
__global__ void k_count(const int* __restrict__ ei, int E) {
    int e = blockIdx.x * blockDim.x + threadIdx.x;
    if (e < E) atomicAdd(&g_cnt[ei[E + e]], 1);
}

// ---------------------------------------------------------------------------
// Exclusive prefix sum over g_cnt -> g_off  (single block, 1024 threads)
// ---------------------------------------------------------------------------
__global__ void k_scan(int N) {
    __shared__ int part[1024];
    int t = threadIdx.x;
    int per = (N + 1023) / 1024;
    int lo = t * per;
    int hi = min(lo + per, N);
    int sum = 0;
    for (int i = lo; i < hi; i++) sum += g_cnt[i];
    part[t] = sum;
    __syncthreads();
    for (int o = 1; o < 1024; o <<= 1) {
        int v = (t >= o) ? part[t - o] : 0;
        __syncthreads();
        part[t] += v;
        __syncthreads();
    }
    int run = (t == 0) ? 0 : part[t - 1];
    for (int i = lo; i < hi; i++) {
        g_off[i] = run;
        run += g_cnt[i];
    }
}

// ---------------------------------------------------------------------------
// Scatter edges into CSR-by-dst order
// ---------------------------------------------------------------------------
__global__ void k_scatter(const int* __restrict__ ei, int E) {
    int e = blockIdx.x * blockDim.x + threadIdx.x;
    if (e >= E) return;
    int s = ei[e];
    int d = ei[E + e];
    int pos = g_off[d] + atomicAdd(&g_cur[d], 1);
    g_csr_src[pos] = s;
}

// ---------------------------------------------------------------------------
// Fused softmax + weighted aggregate + bias + ELU.
// One block per destination node, 128 threads (thread = output column,
// head = t>>5). Self-loop handled virtually. No atomics.
// ---------------------------------------------------------------------------
__global__ void k_agg(float* __restrict__ out, const float* __restrict__ bias, int N) {
    int d = blockIdx.x;
    if (d >= N) return;
    int t = threadIdx.x;
    int head = t >> 5;

    int start = g_off[d];
    int deg = g_cnt[d];

    float4 ad = *(const float4*)&g_ad[d * HEADS];
    float4 asd = *(const float4*)&g_as[d * HEADS];
    float4 lself = leaky4(asd, ad);

    __shared__ float4 red[128];
    __shared__ int s_src[CHUNK];
    __shared__ float s_w[CHUNK * HEADS];

    // Phase A: block max of logits (self-loop included as init)
    float4 mx = lself;
    for (int i = t; i < deg; i += 128) {
        int s = g_csr_src[start + i];
        float4 as = *(const float4*)&g_as[s * HEADS];
        mx = max4(mx, leaky4(as, ad));
    }
    red[t] = mx;
    __syncthreads();
#pragma unroll
    for (int o = 64; o > 0; o >>= 1) {
        if (t < o) red[t] = max4(red[t], red[t + o]);
        __syncthreads();
    }
    float4 bmax = red[0];
    __syncthreads();

    // Phase B: chunked exp weights + denominator + gather-accumulate
    float acc = 0.0f;
    float4 dpart = make_float4(0.f, 0.f, 0.f, 0.f);
    for (int base = 0; base < deg; base += CHUNK) {
        int m = min(CHUNK, deg - base);
        if (t < m) {
            int s = g_csr_src[start + base + t];
            s_src[t] = s;
            float4 as = *(const float4*)&g_as[s * HEADS];
            float4 w = exp4(leaky4(as, ad), bmax);
            s_w[t * HEADS + 0] = w.x;
            s_w[t * HEADS + 1] = w.y;
            s_w[t * HEADS + 2] = w.z;
            s_w[t * HEADS + 3] = w.w;
            dpart.x += w.x; dpart.y += w.y; dpart.z += w.z; dpart.w += w.w;
        }
        __syncthreads();
#pragma unroll 4
        for (int e = 0; e < m; e++) {
            float wt = s_w[e * HEADS + head];
            acc = fmaf(wt, g_h[(long long)s_src[e] * OUTC + t], acc);
        }
        __syncthreads();
    }

    // Self-loop contribution
    float4 wself = exp4(lself, bmax);
    acc = fmaf(sel4(wself, head), g_h[(long long)d * OUTC + t], acc);
    if (t == 0) {
        dpart.x += wself.x; dpart.y += wself.y;
        dpart.z += wself.z; dpart.w += wself.w;
    }

    // Denominator reduce
    red[t] = dpart;
    __syncthreads();
#pragma unroll
    for (int o = 64; o > 0; o >>= 1) {
        if (t < o) {
            float4 a = red[t], b = red[t + o];
            a.x += b.x; a.y += b.y; a.z += b.z; a.w += b.w;
            red[t] = a;
        }
        __syncthreads();
    }
    float denom = sel4(red[0], head) + 1e-16f;

    float v = acc / denom + __ldg(&bias[t]);
    out[(long long)d * OUTC + t] = v > 0.0f ? v : expm1f(v);
}

// ---------------------------------------------------------------------------
extern "C" void kernel_launch(void* const* d_in, const int* in_sizes, int n_in,
                              void* d_out, int out_size) {
    const float* x = (const float*)d_in[0];
    const int* ei = (const int*)d_in[1];   // int32 (jax downcasts int64 w/o x64)
    const float* W = (const float*)d_in[2];
    const float* att_s = (const float*)d_in[3];
    const float* att_d = (const float*)d_in[4];
    const float* bias = (const float*)d_in[5];
    float* out = (float*)d_out;

    int N = in_sizes[0] / INCH;
    int E = in_sizes[1] / 2;
    if (N > NNODES) N = NNODES;
    if (E > NEDGES) E = NEDGES;

    k_zero<<<(N + 255) / 256, 256>>>(N);
    k_proj<<<N, 128>>>(x, W, att_s, att_d, N);
    k_count<<<(E + 255) / 256, 256>>>(ei, E);
    k_scan<<<1, 1024>>>(N);
    k_scatter<<<(E + 255) / 256, 256>>>(ei, E);
    k_agg<<<N, 128>>>(out, bias, N);
}

// round 4
// speedup vs baseline: 2.3173x; 1.4630x over previous
#include <cuda_runtime.h>
#include <math.h>

#define NNODES 50000
#define NEDGES 1600000
#define INCH   128
#define HEADS  4
#define OUTC   128
#define NEG_SLOPE 0.2f
#define CHUNK  128
#define SCAN_B 1024
#define MAXBLK 64

// Scratch (static device globals; no allocation allowed)
__device__ float g_h[NNODES * OUTC];          // projected features [N,128]
__device__ float g_as[NNODES * HEADS];        // a_src [N,4]
__device__ float g_ad[NNODES * HEADS];        // a_dst [N,4]
__device__ int   g_cnt[NNODES];               // in-degree (w/o self loop)
__device__ int   g_off[NNODES];               // CSR offsets (exclusive scan)
__device__ int   g_cur[NNODES];               // scatter cursors
__device__ int   g_csr_src[NEDGES];           // src node per CSR slot
__device__ int   g_bsum[MAXBLK];              // scan block partials
__device__ int   g_boff[MAXBLK];              // scan block offsets

__device__ __forceinline__ float leaky(float v) {
    return v > 0.0f ? v : NEG_SLOPE * v;
}
__device__ __forceinline__ float4 expleaky4(float4 a, float4 b) {
    float4 r;
    r.x = __expf(leaky(a.x + b.x)); r.y = __expf(leaky(a.y + b.y));
    r.z = __expf(leaky(a.z + b.z)); r.w = __expf(leaky(a.w + b.w));
    return r;
}
__device__ __forceinline__ float sel4(float4 v, int h) {
    return h == 0 ? v.x : h == 1 ? v.y : h == 2 ? v.z : v.w;
}

// ---------------------------------------------------------------------------
__global__ void k_zero(int N) {
    int i = blockIdx.x * blockDim.x + threadIdx.x;
    if (i < N) { g_cnt[i] = 0; g_cur[i] = 0; }
}

// ---------------------------------------------------------------------------
// Projection + logits. Block = 128 threads = 4 nodes (1 warp/node).
// Lane owns 4 consecutive output columns -> LDG.128 on W.
// ---------------------------------------------------------------------------
__global__ void k_proj(const float* __restrict__ x, const float* __restrict__ W,
                       const float* __restrict__ att_s, const float* __restrict__ att_d,
                       int N) {
    int warp = threadIdx.x >> 5;
    int lane = threadIdx.x & 31;
    int n = blockIdx.x * 4 + warp;
    if (n >= N) return;

    __shared__ float xs[4][INCH];
    *(float4*)&xs[warp][lane * 4] = *(const float4*)&x[n * INCH + lane * 4];
    __syncwarp();

    float4 acc = make_float4(0.f, 0.f, 0.f, 0.f);
#pragma unroll 8
    for (int k = 0; k < INCH; k++) {
        float xv = xs[warp][k];
        float4 w4 = *(const float4*)&W[k * OUTC + lane * 4];
        acc.x = fmaf(xv, w4.x, acc.x);
        acc.y = fmaf(xv, w4.y, acc.y);
        acc.z = fmaf(xv, w4.z, acc.z);
        acc.w = fmaf(xv, w4.w, acc.w);
    }
    *(float4*)&g_h[(long long)n * OUTC + lane * 4] = acc;

    // attention logits: head = lane>>3 (cols 4*lane..4*lane+3 same head)
    float4 s4 = *(const float4*)&att_s[lane * 4];
    float4 d4 = *(const float4*)&att_d[lane * 4];
    float vs = acc.x * s4.x + acc.y * s4.y + acc.z * s4.z + acc.w * s4.w;
    float vd = acc.x * d4.x + acc.y * d4.y + acc.z * d4.z + acc.w * d4.w;
    // reduce within each 8-lane head group
#pragma unroll
    for (int o = 4; o > 0; o >>= 1) {
        vs += __shfl_down_sync(0xffffffffu, vs, o);
        vd += __shfl_down_sync(0xffffffffu, vd, o);
    }
    if ((lane & 7) == 0) {
        int h = lane >> 3;
        g_as[n * HEADS + h] = vs;
        g_ad[n * HEADS + h] = vd;
    }
}

// ---------------------------------------------------------------------------
__global__ void k_count(const int* __restrict__ ei, int E) {
    int e = blockIdx.x * blockDim.x + threadIdx.x;
    if (e < E) atomicAdd(&g_cnt[ei[E + e]], 1);
}

// ---------------------------------------------------------------------------
// Parallel scan, 3 phases. SCAN_B=1024 elems per block, 256 threads.
// ---------------------------------------------------------------------------
__global__ void k_scan1(int N) {
    int t = threadIdx.x;
    int i0 = blockIdx.x * SCAN_B + t * 4;
    int s = 0;
#pragma unroll
    for (int j = 0; j < 4; j++)
        if (i0 + j < N) s += g_cnt[i0 + j];
    __shared__ int sh[256];
    sh[t] = s;
    __syncthreads();
#pragma unroll
    for (int o = 128; o > 0; o >>= 1) {
        if (t < o) sh[t] += sh[t + o];
        __syncthreads();
    }
    if (t == 0) g_bsum[blockIdx.x] = sh[0];
}

__global__ void k_scan2(int NB) {
    int t = threadIdx.x; // 64 threads
    __shared__ int sh[MAXBLK];
    sh[t] = (t < NB) ? g_bsum[t] : 0;
    __syncthreads();
#pragma unroll
    for (int o = 1; o < MAXBLK; o <<= 1) {
        int v = (t >= o) ? sh[t - o] : 0;
        __syncthreads();
        sh[t] += v;
        __syncthreads();
    }
    if (t < NB) g_boff[t] = (t == 0) ? 0 : sh[t - 1];
}

__global__ void k_scan3(int N) {
    int t = threadIdx.x;
    int i0 = blockIdx.x * SCAN_B + t * 4;
    int v[4];
    int s = 0;
#pragma unroll
    for (int j = 0; j < 4; j++) {
        v[j] = (i0 + j < N) ? g_cnt[i0 + j] : 0;
        s += v[j];
    }
    __shared__ int sh[256];
    sh[t] = s;
    __syncthreads();
    for (int o = 1; o < 256; o <<= 1) {
        int u = (t >= o) ? sh[t - o] : 0;
        __syncthreads();
        sh[t] += u;
        __syncthreads();
    }
    int run = g_boff[blockIdx.x] + ((t == 0) ? 0 : sh[t - 1]);
#pragma unroll
    for (int j = 0; j < 4; j++) {
        if (i0 + j < N) g_off[i0 + j] = run;
        run += v[j];
    }
}

// ---------------------------------------------------------------------------
__global__ void k_scatter(const int* __restrict__ ei, int E) {
    int e = blockIdx.x * blockDim.x + threadIdx.x;
    if (e >= E) return;
    int s = ei[e];
    int d = ei[E + e];
    int pos = g_off[d] + atomicAdd(&g_cur[d], 1);
    g_csr_src[pos] = s;
}

// ---------------------------------------------------------------------------
// Fused softmax (no max-shift; softmax is shift-invariant, logits O(1)) +
// weighted aggregate + bias + ELU. Block = 128 threads per destination node.
// Feature phase: warp-per-edge, lane owns 4 cols via LDG.128.
// ---------------------------------------------------------------------------
__global__ void k_agg(float* __restrict__ out, const float* __restrict__ bias, int N) {
    int d = blockIdx.x;
    if (d >= N) return;
    int t = threadIdx.x;
    int warp = t >> 5;
    int lane = t & 31;
    int head = lane >> 3; // head of cols 4*lane..4*lane+3

    int start = g_off[d];
    int deg = g_cnt[d];

    float4 ad4 = *(const float4*)&g_ad[d * HEADS];
    float4 asd = *(const float4*)&g_as[d * HEADS];
    float4 wself = expleaky4(asd, ad4);

    __shared__ int s_src[CHUNK];
    __shared__ float s_w[CHUNK][HEADS];
    __shared__ float4 red[128];           // denom reduce
    __shared__ float4 s_acc[4][32];       // cross-warp feature reduce

    float4 acc = make_float4(0.f, 0.f, 0.f, 0.f);
    float4 dpart = make_float4(0.f, 0.f, 0.f, 0.f);

    for (int base = 0; base < deg; base += CHUNK) {
        int m = min(CHUNK, deg - base);
        if (t < m) {
            int s = g_csr_src[start + base + t];
            s_src[t] = s;
            float4 as = *(const float4*)&g_as[s * HEADS];
            float4 w = expleaky4(as, ad4);
            s_w[t][0] = w.x; s_w[t][1] = w.y; s_w[t][2] = w.z; s_w[t][3] = w.w;
            dpart.x += w.x; dpart.y += w.y; dpart.z += w.z; dpart.w += w.w;
        }
        __syncthreads();
        for (int e = warp; e < m; e += 4) {
            int s = s_src[e];
            float wt = s_w[e][head];
            float4 h4 = *(const float4*)&g_h[(long long)s * OUTC + lane * 4];
            acc.x = fmaf(wt, h4.x, acc.x);
            acc.y = fmaf(wt, h4.y, acc.y);
            acc.z = fmaf(wt, h4.z, acc.z);
            acc.w = fmaf(wt, h4.w, acc.w);
        }
        __syncthreads();
    }

    // self-loop: feature on warp 0, weight on thread 0
    if (warp == 0) {
        float wt = sel4(wself, head);
        float4 h4 = *(const float4*)&g_h[(long long)d * OUTC + lane * 4];
        acc.x = fmaf(wt, h4.x, acc.x);
        acc.y = fmaf(wt, h4.y, acc.y);
        acc.z = fmaf(wt, h4.z, acc.z);
        acc.w = fmaf(wt, h4.w, acc.w);
    }
    if (t == 0) {
        dpart.x += wself.x; dpart.y += wself.y;
        dpart.z += wself.z; dpart.w += wself.w;
    }

    // denominator reduce (block-wide)
    red[t] = dpart;
    __syncthreads();
#pragma unroll
    for (int o = 64; o > 0; o >>= 1) {
        if (t < o) {
            float4 a = red[t], b = red[t + o];
            a.x += b.x; a.y += b.y; a.z += b.z; a.w += b.w;
            red[t] = a;
        }
        __syncthreads();
    }
    float4 den4 = red[0];

    // cross-warp feature reduce + epilogue
    s_acc[warp][lane] = acc;
    __syncthreads();
    if (t < 32) {
        float4 a = s_acc[0][t], b = s_acc[1][t], c = s_acc[2][t], e4 = s_acc[3][t];
        a.x += b.x + c.x + e4.x;
        a.y += b.y + c.y + e4.y;
        a.z += b.z + c.z + e4.z;
        a.w += b.w + c.w + e4.w;
        float den = sel4(den4, t >> 3) + 1e-16f;
        float4 b4 = *(const float4*)&bias[t * 4];
        float4 v;
        v.x = a.x / den + b4.x;
        v.y = a.y / den + b4.y;
        v.z = a.z / den + b4.z;
        v.w = a.w / den + b4.w;
        v.x = v.x > 0.f ? v.x : expm1f(v.x);
        v.y = v.y > 0.f ? v.y : expm1f(v.y);
        v.z = v.z > 0.f ? v.z : expm1f(v.z);
        v.w = v.w > 0.f ? v.w : expm1f(v.w);
        *(float4*)&out[(long long)d * OUTC + t * 4] = v;
    }
}

// ---------------------------------------------------------------------------
extern "C" void kernel_launch(void* const* d_in, const int* in_sizes, int n_in,
                              void* d_out, int out_size) {
    const float* x = (const float*)d_in[0];
    const int* ei = (const int*)d_in[1];   // int32 (jax downcasts int64 w/o x64)
    const float* W = (const float*)d_in[2];
    const float* att_s = (const float*)d_in[3];
    const float* att_d = (const float*)d_in[4];
    const float* bias = (const float*)d_in[5];
    float* out = (float*)d_out;

    int N = in_sizes[0] / INCH;
    int E = in_sizes[1] / 2;
    if (N > NNODES) N = NNODES;
    if (E > NEDGES) E = NEDGES;
    int NB = (N + SCAN_B - 1) / SCAN_B;

    k_zero<<<(N + 255) / 256, 256>>>(N);
    k_proj<<<(N + 3) / 4, 128>>>(x, W, att_s, att_d, N);
    k_count<<<(E + 255) / 256, 256>>>(ei, E);
    k_scan1<<<NB, 256>>>(N);
    k_scan2<<<1, MAXBLK>>>(NB);
    k_scan3<<<NB, 256>>>(N);
    k_scatter<<<(E + 255) / 256, 256>>>(ei, E);
    k_agg<<<N, 128>>>(out, bias, N);
}

// round 5
// speedup vs baseline: 3.2811x; 1.4159x over previous
#include <cuda_runtime.h>
#include <math.h>

#define NNODES 50000
#define NEDGES 1600000
#define INCH   128
#define HEADS  4
#define OUTC   128
#define NEG_SLOPE 0.2f
#define SCAN_B 1024
#define MAXBLK 64

// Scratch (static device globals; no allocation allowed)
__device__ float g_h[NNODES * OUTC];          // projected features [N,128]
__device__ float g_as[NNODES * HEADS];        // a_src [N,4]
__device__ float g_ad[NNODES * HEADS];        // a_dst [N,4]
__device__ int   g_cnt[NNODES];               // in-degree (w/o self loop)
__device__ int   g_off[NNODES];               // CSR offsets (exclusive scan)
__device__ int   g_cur[NNODES];               // scatter cursors
__device__ int   g_csr_src[NEDGES];           // src node per CSR slot
__device__ int   g_bsum[MAXBLK];              // scan block partials
__device__ int   g_boff[MAXBLK];              // scan block offsets

__device__ __forceinline__ float leaky(float v) {
    return v > 0.0f ? v : NEG_SLOPE * v;
}
__device__ __forceinline__ float4 expleaky4(float4 a, float4 b) {
    float4 r;
    r.x = __expf(leaky(a.x + b.x)); r.y = __expf(leaky(a.y + b.y));
    r.z = __expf(leaky(a.z + b.z)); r.w = __expf(leaky(a.w + b.w));
    return r;
}
__device__ __forceinline__ float sel4(float4 v, int h) {
    return h == 0 ? v.x : h == 1 ? v.y : h == 2 ? v.z : v.w;
}

// packed fp32x2 helpers (full fp32 precision; FFMA2 only reachable via PTX)
__device__ __forceinline__ unsigned long long pack2(float a, float b) {
    unsigned long long r;
    asm("mov.b64 %0, {%1, %2};" : "=l"(r) : "f"(a), "f"(b));
    return r;
}
__device__ __forceinline__ unsigned long long dup2(float a) {
    unsigned long long r;
    asm("mov.b64 %0, {%1, %1};" : "=l"(r) : "f"(a));
    return r;
}
__device__ __forceinline__ void fma2(unsigned long long& d, unsigned long long a,
                                     unsigned long long b) {
    asm("fma.rn.f32x2 %0, %1, %2, %0;" : "+l"(d) : "l"(a), "l"(b));
}
__device__ __forceinline__ void unpack2(unsigned long long v, float& lo, float& hi) {
    asm("mov.b64 {%0, %1}, %2;" : "=f"(lo), "=f"(hi) : "l"(v));
}

// ---------------------------------------------------------------------------
__global__ void k_zero(int N) {
    int i = blockIdx.x * blockDim.x + threadIdx.x;
    if (i < N) { g_cnt[i] = 0; g_cur[i] = 0; }
}

// ---------------------------------------------------------------------------
// Projection + logits. Block = 256 threads = 8 warps; each warp computes
// 8 nodes x 128 cols (lane owns 4 consecutive cols). W float4 reused across
// 8 nodes -> 8x less L1 traffic; packed f32x2 FMA halves fma-pipe ops.
// ---------------------------------------------------------------------------
__global__ void k_proj(const float* __restrict__ x, const float* __restrict__ W,
                       const float* __restrict__ att_s, const float* __restrict__ att_d,
                       int N) {
    __shared__ float xs[64][INCH];  // 32 KB
    int t = threadIdx.x;
    int n0 = blockIdx.x * 64;
    int nvalid = min(64, N - n0);

    // coalesced stage of x (zero-fill tail so garbage never reaches exp paths)
    for (int i = t * 4; i < 64 * INCH; i += 256 * 4) {
        float4 v = make_float4(0.f, 0.f, 0.f, 0.f);
        if (i < nvalid * INCH) v = *(const float4*)&x[(long long)n0 * INCH + i];
        *(float4*)&xs[0][i] = v;
    }
    __syncthreads();

    int warp = t >> 5;
    int lane = t & 31;
    int nb = warp * 8;  // first node (within block) for this warp

    unsigned long long a01[8], a23[8];
#pragma unroll
    for (int j = 0; j < 8; j++) { a01[j] = 0ull; a23[j] = 0ull; }

#pragma unroll 4
    for (int k = 0; k < INCH; k++) {
        float4 w4 = *(const float4*)&W[k * OUTC + lane * 4];
        unsigned long long w01 = pack2(w4.x, w4.y);
        unsigned long long w23 = pack2(w4.z, w4.w);
#pragma unroll
        for (int j = 0; j < 8; j++) {
            unsigned long long xx = dup2(xs[nb + j][k]);
            fma2(a01[j], w01, xx);
            fma2(a23[j], w23, xx);
        }
    }

    float4 s4 = *(const float4*)&att_s[lane * 4];
    float4 d4 = *(const float4*)&att_d[lane * 4];

#pragma unroll
    for (int j = 0; j < 8; j++) {
        int n = n0 + nb + j;
        float4 acc;
        unpack2(a01[j], acc.x, acc.y);
        unpack2(a23[j], acc.z, acc.w);
        if (n < N)
            *(float4*)&g_h[(long long)n * OUTC + lane * 4] = acc;

        float vs = acc.x * s4.x + acc.y * s4.y + acc.z * s4.z + acc.w * s4.w;
        float vd = acc.x * d4.x + acc.y * d4.y + acc.z * d4.z + acc.w * d4.w;
#pragma unroll
        for (int o = 4; o > 0; o >>= 1) {
            vs += __shfl_down_sync(0xffffffffu, vs, o);
            vd += __shfl_down_sync(0xffffffffu, vd, o);
        }
        if ((lane & 7) == 0 && n < N) {
            int h = lane >> 3;
            g_as[n * HEADS + h] = vs;
            g_ad[n * HEADS + h] = vd;
        }
    }
}

// ---------------------------------------------------------------------------
__global__ void k_count(const int* __restrict__ ei, int E) {
    int e = blockIdx.x * blockDim.x + threadIdx.x;
    if (e < E) atomicAdd(&g_cnt[ei[E + e]], 1);
}

// ---------------------------------------------------------------------------
// Parallel scan, 3 phases.
// ---------------------------------------------------------------------------
__global__ void k_scan1(int N) {
    int t = threadIdx.x;
    int i0 = blockIdx.x * SCAN_B + t * 4;
    int s = 0;
#pragma unroll
    for (int j = 0; j < 4; j++)
        if (i0 + j < N) s += g_cnt[i0 + j];
    __shared__ int sh[256];
    sh[t] = s;
    __syncthreads();
#pragma unroll
    for (int o = 128; o > 0; o >>= 1) {
        if (t < o) sh[t] += sh[t + o];
        __syncthreads();
    }
    if (t == 0) g_bsum[blockIdx.x] = sh[0];
}

__global__ void k_scan2(int NB) {
    int t = threadIdx.x; // 64 threads
    __shared__ int sh[MAXBLK];
    sh[t] = (t < NB) ? g_bsum[t] : 0;
    __syncthreads();
#pragma unroll
    for (int o = 1; o < MAXBLK; o <<= 1) {
        int v = (t >= o) ? sh[t - o] : 0;
        __syncthreads();
        sh[t] += v;
        __syncthreads();
    }
    if (t < NB) g_boff[t] = (t == 0) ? 0 : sh[t - 1];
}

__global__ void k_scan3(int N) {
    int t = threadIdx.x;
    int i0 = blockIdx.x * SCAN_B + t * 4;
    int v[4];
    int s = 0;
#pragma unroll
    for (int j = 0; j < 4; j++) {
        v[j] = (i0 + j < N) ? g_cnt[i0 + j] : 0;
        s += v[j];
    }
    __shared__ int sh[256];
    sh[t] = s;
    __syncthreads();
    for (int o = 1; o < 256; o <<= 1) {
        int u = (t >= o) ? sh[t - o] : 0;
        __syncthreads();
        sh[t] += u;
        __syncthreads();
    }
    int run = g_boff[blockIdx.x] + ((t == 0) ? 0 : sh[t - 1]);
#pragma unroll
    for (int j = 0; j < 4; j++) {
        if (i0 + j < N) g_off[i0 + j] = run;
        run += v[j];
    }
}

// ---------------------------------------------------------------------------
__global__ void k_scatter(const int* __restrict__ ei, int E) {
    int e = blockIdx.x * blockDim.x + threadIdx.x;
    if (e >= E) return;
    int s = ei[e];
    int d = ei[E + e];
    int pos = g_off[d] + atomicAdd(&g_cur[d], 1);
    g_csr_src[pos] = s;
}

// ---------------------------------------------------------------------------
// Fused softmax + weighted aggregate + bias + ELU. WARP per destination node
// (mean degree 32, no heavy skew). Lane owns 4 cols (LDG.128 gather); weights
// staged in a per-warp smem tile; denominator via per-lane partials +
// butterfly reduce. No block syncs, no atomics.
// ---------------------------------------------------------------------------
__global__ void k_agg(float* __restrict__ out, const float* __restrict__ bias, int N) {
    int warp = threadIdx.x >> 5;  // 8 warps/block
    int lane = threadIdx.x & 31;
    int d = blockIdx.x * 8 + warp;
    if (d >= N) return;
    int head = lane >> 3;

    int start = g_off[d];
    int deg = g_cnt[d];

    float4 ad4 = *(const float4*)&g_ad[d * HEADS];
    float4 asd = *(const float4*)&g_as[d * HEADS];
    float4 wself = expleaky4(asd, ad4);

    __shared__ float s_w[8][32][HEADS];  // 4 KB

    // self-loop
    float4 den = (lane == 0) ? wself
                             : make_float4(0.f, 0.f, 0.f, 0.f);
    float wts = sel4(wself, head);
    float4 h4 = *(const float4*)&g_h[(long long)d * OUTC + lane * 4];
    float4 acc;
    acc.x = wts * h4.x; acc.y = wts * h4.y;
    acc.z = wts * h4.z; acc.w = wts * h4.w;

    for (int base = 0; base < deg; base += 32) {
        int m = min(32, deg - base);
        int s = 0;
        float4 w = make_float4(0.f, 0.f, 0.f, 0.f);
        if (lane < m) {
            s = g_csr_src[start + base + lane];
            float4 as4 = *(const float4*)&g_as[s * HEADS];
            w = expleaky4(as4, ad4);
            den.x += w.x; den.y += w.y; den.z += w.z; den.w += w.w;
        }
        *(float4*)&s_w[warp][lane][0] = w;
        __syncwarp();
#pragma unroll 4
        for (int e = 0; e < m; e++) {
            int se = __shfl_sync(0xffffffffu, s, e);
            float wt = s_w[warp][e][head];
            float4 hh = *(const float4*)&g_h[(long long)se * OUTC + lane * 4];
            acc.x = fmaf(wt, hh.x, acc.x);
            acc.y = fmaf(wt, hh.y, acc.y);
            acc.z = fmaf(wt, hh.z, acc.z);
            acc.w = fmaf(wt, hh.w, acc.w);
        }
        __syncwarp();
    }

    // butterfly reduce denominator (all lanes end with full sums)
#pragma unroll
    for (int o = 16; o > 0; o >>= 1) {
        den.x += __shfl_xor_sync(0xffffffffu, den.x, o);
        den.y += __shfl_xor_sync(0xffffffffu, den.y, o);
        den.z += __shfl_xor_sync(0xffffffffu, den.z, o);
        den.w += __shfl_xor_sync(0xffffffffu, den.w, o);
    }
    float denv = sel4(den, head) + 1e-16f;

    float4 b4 = *(const float4*)&bias[lane * 4];
    float4 v;
    v.x = acc.x / denv + b4.x;
    v.y = acc.y / denv + b4.y;
    v.z = acc.z / denv + b4.z;
    v.w = acc.w / denv + b4.w;
    v.x = v.x > 0.f ? v.x : expm1f(v.x);
    v.y = v.y > 0.f ? v.y : expm1f(v.y);
    v.z = v.z > 0.f ? v.z : expm1f(v.z);
    v.w = v.w > 0.f ? v.w : expm1f(v.w);
    *(float4*)&out[(long long)d * OUTC + lane * 4] = v;
}

// ---------------------------------------------------------------------------
extern "C" void kernel_launch(void* const* d_in, const int* in_sizes, int n_in,
                              void* d_out, int out_size) {
    const float* x = (const float*)d_in[0];
    const int* ei = (const int*)d_in[1];   // int32 (jax downcasts int64 w/o x64)
    const float* W = (const float*)d_in[2];
    const float* att_s = (const float*)d_in[3];
    const float* att_d = (const float*)d_in[4];
    const float* bias = (const float*)d_in[5];
    float* out = (float*)d_out;

    int N = in_sizes[0] / INCH;
    int E = in_sizes[1] / 2;
    if (N > NNODES) N = NNODES;
    if (E > NEDGES) E = NEDGES;
    int NB = (N + SCAN_B - 1) / SCAN_B;

    k_zero<<<(N + 255) / 256, 256>>>(N);
    k_proj<<<(N + 63) / 64, 256>>>(x, W, att_s, att_d, N);
    k_count<<<(E + 255) / 256, 256>>>(ei, E);
    k_scan1<<<NB, 256>>>(N);
    k_scan2<<<1, MAXBLK>>>(NB);
    k_scan3<<<NB, 256>>>(N);
    k_scatter<<<(E + 255) / 256, 256>>>(ei, E);
    k_agg<<<(N + 7) / 8, 256>>>(out, bias, N);
}

// round 7
// speedup vs baseline: 3.5606x; 1.0852x over previous
#include <cuda_runtime.h>
#include <cuda_fp16.h>
#include <math.h>

#define NNODES 50000
#define NEDGES 1600000
#define INCH   128
#define HEADS  4
#define OUTC   128
#define NEG_SLOPE 0.2f
#define SCAN_B 1024
#define MAXBLK 64

// Scratch (static device globals; no allocation allowed)
__device__ __half2 g_hb[NNODES * OUTC / 2];   // projected features, fp16x2 [N,64]
__device__ float g_as[NNODES * HEADS];        // a_src [N,4]
__device__ float g_ad[NNODES * HEADS];        // a_dst [N,4]
__device__ int   g_cnt[NNODES];               // in-degree (w/o self loop)
__device__ int   g_off[NNODES];               // CSR offsets (exclusive scan)
__device__ int   g_cur[NNODES];               // scatter cursors
__device__ int   g_csr_src[NEDGES];           // src node per CSR slot
__device__ int   g_bsum[MAXBLK];              // scan block partials
__device__ int   g_boff[MAXBLK];              // scan block offsets

__device__ __forceinline__ float leaky(float v) {
    return v > 0.0f ? v : NEG_SLOPE * v;
}
__device__ __forceinline__ float4 expleaky4(float4 a, float4 b) {
    float4 r;
    r.x = __expf(leaky(a.x + b.x)); r.y = __expf(leaky(a.y + b.y));
    r.z = __expf(leaky(a.z + b.z)); r.w = __expf(leaky(a.w + b.w));
    return r;
}
__device__ __forceinline__ float sel4(float4 v, int h) {
    return h == 0 ? v.x : h == 1 ? v.y : h == 2 ? v.z : v.w;
}

// packed fp32x2 helpers (FFMA2 only reachable via PTX)
__device__ __forceinline__ unsigned long long pack2(float a, float b) {
    unsigned long long r;
    asm("mov.b64 %0, {%1, %2};" : "=l"(r) : "f"(a), "f"(b));
    return r;
}
__device__ __forceinline__ unsigned long long dup2(float a) {
    unsigned long long r;
    asm("mov.b64 %0, {%1, %1};" : "=l"(r) : "f"(a));
    return r;
}
__device__ __forceinline__ void fma2(unsigned long long& d, unsigned long long a,
                                     unsigned long long b) {
    asm("fma.rn.f32x2 %0, %1, %2, %0;" : "+l"(d) : "l"(a), "l"(b));
}
__device__ __forceinline__ void unpack2(unsigned long long v, float& lo, float& hi) {
    asm("mov.b64 {%0, %1}, %2;" : "=f"(lo), "=f"(hi) : "l"(v));
}

// ---------------------------------------------------------------------------
__global__ void k_zero(int N) {
    int i = blockIdx.x * blockDim.x + threadIdx.x;
    if (i < N) g_cnt[i] = 0;
}

// ---------------------------------------------------------------------------
// Projection + logits + fused degree histogram.
// Block = 256 threads = 8 warps; each warp computes 8 nodes x 128 cols.
// ---------------------------------------------------------------------------
__global__ void k_proj(const float* __restrict__ x, const float* __restrict__ W,
                       const float* __restrict__ att_s, const float* __restrict__ att_d,
                       const int* __restrict__ ei, int N, int E) {
    __shared__ float xs[64][INCH];  // 32 KB
    int t = threadIdx.x;
    int n0 = blockIdx.x * 64;
    int nvalid = min(64, N - n0);

    for (int i = t * 4; i < 64 * INCH; i += 256 * 4) {
        float4 v = make_float4(0.f, 0.f, 0.f, 0.f);
        if (i < nvalid * INCH) v = *(const float4*)&x[(long long)n0 * INCH + i];
        *(float4*)&xs[0][i] = v;
    }
    __syncthreads();

    int warp = t >> 5;
    int lane = t & 31;
    int nb = warp * 8;

    unsigned long long a01[8], a23[8];
#pragma unroll
    for (int j = 0; j < 8; j++) { a01[j] = 0ull; a23[j] = 0ull; }

#pragma unroll 4
    for (int k = 0; k < INCH; k++) {
        float4 w4 = *(const float4*)&W[k * OUTC + lane * 4];
        unsigned long long w01 = pack2(w4.x, w4.y);
        unsigned long long w23 = pack2(w4.z, w4.w);
#pragma unroll
        for (int j = 0; j < 8; j++) {
            unsigned long long xx = dup2(xs[nb + j][k]);
            fma2(a01[j], w01, xx);
            fma2(a23[j], w23, xx);
        }
    }

    float4 s4 = *(const float4*)&att_s[lane * 4];
    float4 d4 = *(const float4*)&att_d[lane * 4];

#pragma unroll
    for (int j = 0; j < 8; j++) {
        int n = n0 + nb + j;
        float4 acc;
        unpack2(a01[j], acc.x, acc.y);
        unpack2(a23[j], acc.z, acc.w);
        if (n < N) {
            __half2 p0 = __float22half2_rn(make_float2(acc.x, acc.y));
            __half2 p1 = __float22half2_rn(make_float2(acc.z, acc.w));
            uint2 p;
            p.x = *(unsigned int*)&p0;
            p.y = *(unsigned int*)&p1;
            *(uint2*)&g_hb[(long long)n * (OUTC / 2) + lane * 2] = p;
        }

        float vs = acc.x * s4.x + acc.y * s4.y + acc.z * s4.z + acc.w * s4.w;
        float vd = acc.x * d4.x + acc.y * d4.y + acc.z * d4.z + acc.w * d4.w;
#pragma unroll
        for (int o = 4; o > 0; o >>= 1) {
            vs += __shfl_down_sync(0xffffffffu, vs, o);
            vd += __shfl_down_sync(0xffffffffu, vd, o);
        }
        if ((lane & 7) == 0 && n < N) {
            int h = lane >> 3;
            g_as[n * HEADS + h] = vs;
            g_ad[n * HEADS + h] = vd;
        }
    }

    // fused degree histogram (grid-stride)
    int stride = gridDim.x * 256;
    for (int e = blockIdx.x * 256 + t; e < E; e += stride)
        atomicAdd(&g_cnt[ei[E + e]], 1);
}

// ---------------------------------------------------------------------------
// Parallel scan, 3 phases.
// ---------------------------------------------------------------------------
__global__ void k_scan1(int N) {
    int t = threadIdx.x;
    int i0 = blockIdx.x * SCAN_B + t * 4;
    int s = 0;
#pragma unroll
    for (int j = 0; j < 4; j++)
        if (i0 + j < N) s += g_cnt[i0 + j];
    __shared__ int sh[256];
    sh[t] = s;
    __syncthreads();
#pragma unroll
    for (int o = 128; o > 0; o >>= 1) {
        if (t < o) sh[t] += sh[t + o];
        __syncthreads();
    }
    if (t == 0) g_bsum[blockIdx.x] = sh[0];
}

__global__ void k_scan2(int NB) {
    int t = threadIdx.x; // 64 threads
    __shared__ int sh[MAXBLK];
    sh[t] = (t < NB) ? g_bsum[t] : 0;
    __syncthreads();
#pragma unroll
    for (int o = 1; o < MAXBLK; o <<= 1) {
        int v = (t >= o) ? sh[t - o] : 0;
        __syncthreads();
        sh[t] += v;
        __syncthreads();
    }
    if (t < NB) g_boff[t] = (t == 0) ? 0 : sh[t - 1];
}

__global__ void k_scan3(int N) {
    int t = threadIdx.x;
    int i0 = blockIdx.x * SCAN_B + t * 4;
    int v[4];
    int s = 0;
#pragma unroll
    for (int j = 0; j < 4; j++) {
        v[j] = (i0 + j < N) ? g_cnt[i0 + j] : 0;
        s += v[j];
    }
    __shared__ int sh[256];
    sh[t] = s;
    __syncthreads();
    for (int o = 1; o < 256; o <<= 1) {
        int u = (t >= o) ? sh[t - o] : 0;
        __syncthreads();
        sh[t] += u;
        __syncthreads();
    }
    int run = g_boff[blockIdx.x] + ((t == 0) ? 0 : sh[t - 1]);
#pragma unroll
    for (int j = 0; j < 4; j++) {
        if (i0 + j < N) {
            g_off[i0 + j] = run;
            g_cur[i0 + j] = 0;
        }
        run += v[j];
    }
}

// ---------------------------------------------------------------------------
__global__ void k_scatter(const int* __restrict__ ei, int E) {
    int e = blockIdx.x * blockDim.x + threadIdx.x;
    if (e >= E) return;
    int s = ei[e];
    int d = ei[E + e];
    int pos = g_off[d] + atomicAdd(&g_cur[d], 1);
    g_csr_src[pos] = s;
}

// ---------------------------------------------------------------------------
// Fused softmax + weighted aggregate + bias + ELU. WARP per destination node.
// Features gathered as fp16x2 (LDG.64 per lane), weights via per-warp smem
// tile, denominator via butterfly reduce. No block syncs, no atomics.
// ---------------------------------------------------------------------------
__global__ void k_agg(float* __restrict__ out, const float* __restrict__ bias, int N) {
    int warp = threadIdx.x >> 5;  // 8 warps/block
    int lane = threadIdx.x & 31;
    int d = blockIdx.x * 8 + warp;
    if (d >= N) return;
    int head = lane >> 3;

    int start = g_off[d];
    int deg = g_cnt[d];

    float4 ad4 = *(const float4*)&g_ad[d * HEADS];
    float4 asd = *(const float4*)&g_as[d * HEADS];
    float4 wself = expleaky4(asd, ad4);

    __shared__ float s_w[8][32][HEADS];  // 4 KB

    // self-loop
    float4 den = (lane == 0) ? wself : make_float4(0.f, 0.f, 0.f, 0.f);
    float wts = sel4(wself, head);
    const __half2* hrow = &g_hb[(long long)d * (OUTC / 2) + lane * 2];
    float2 f0 = __half22float2(hrow[0]);
    float2 f1 = __half22float2(hrow[1]);
    float4 acc;
    acc.x = wts * f0.x; acc.y = wts * f0.y;
    acc.z = wts * f1.x; acc.w = wts * f1.y;

    for (int base = 0; base < deg; base += 32) {
        int m = min(32, deg - base);
        int s = 0;
        float4 w = make_float4(0.f, 0.f, 0.f, 0.f);
        if (lane < m) {
            s = g_csr_src[start + base + lane];
            float4 as4 = *(const float4*)&g_as[s * HEADS];
            w = expleaky4(as4, ad4);
            den.x += w.x; den.y += w.y; den.z += w.z; den.w += w.w;
        }
        *(float4*)&s_w[warp][lane][0] = w;
        __syncwarp();
#pragma unroll 8
        for (int e = 0; e < m; e++) {
            int se = __shfl_sync(0xffffffffu, s, e);
            float wt = s_w[warp][e][head];
            uint2 raw = *(const uint2*)&g_hb[(long long)se * (OUTC / 2) + lane * 2];
            float2 g0 = __half22float2(*(__half2*)&raw.x);
            float2 g1 = __half22float2(*(__half2*)&raw.y);
            acc.x = fmaf(wt, g0.x, acc.x);
            acc.y = fmaf(wt, g0.y, acc.y);
            acc.z = fmaf(wt, g1.x, acc.z);
            acc.w = fmaf(wt, g1.y, acc.w);
        }
        __syncwarp();
    }

    // butterfly reduce denominator
#pragma unroll
    for (int o = 16; o > 0; o >>= 1) {
        den.x += __shfl_xor_sync(0xffffffffu, den.x, o);
        den.y += __shfl_xor_sync(0xffffffffu, den.y, o);
        den.z += __shfl_xor_sync(0xffffffffu, den.z, o);
        den.w += __shfl_xor_sync(0xffffffffu, den.w, o);
    }
    float denv = sel4(den, head) + 1e-16f;

    float4 b4 = *(const float4*)&bias[lane * 4];
    float4 v;
    v.x = acc.x / denv + b4.x;
    v.y = acc.y / denv + b4.y;
    v.z = acc.z / denv + b4.z;
    v.w = acc.w / denv + b4.w;
    v.x = v.x > 0.f ? v.x : expm1f(v.x);
    v.y = v.y > 0.f ? v.y : expm1f(v.y);
    v.z = v.z > 0.f ? v.z : expm1f(v.z);
    v.w = v.w > 0.f ? v.w : expm1f(v.w);
    *(float4*)&out[(long long)d * OUTC + lane * 4] = v;
}

// ---------------------------------------------------------------------------
extern "C" void kernel_launch(void* const* d_in, const int* in_sizes, int n_in,
                              void* d_out, int out_size) {
    const float* x = (const float*)d_in[0];
    const int* ei = (const int*)d_in[1];   // int32 (jax downcasts int64 w/o x64)
    const float* W = (const float*)d_in[2];
    const float* att_s = (const float*)d_in[3];
    const float* att_d = (const float*)d_in[4];
    const float* bias = (const float*)d_in[5];
    float* out = (float*)d_out;

    int N = in_sizes[0] / INCH;
    int E = in_sizes[1] / 2;
    if (N > NNODES) N = NNODES;
    if (E > NEDGES) E = NEDGES;
    int NB = (N + SCAN_B - 1) / SCAN_B;

    k_zero<<<(N + 255) / 256, 256>>>(N);
    k_proj<<<(N + 63) / 64, 256>>>(x, W, att_s, att_d, ei, N, E);
    k_scan1<<<NB, 256>>>(N);
    k_scan2<<<1, MAXBLK>>>(NB);
    k_scan3<<<NB, 256>>>(N);
    k_scatter<<<(E + 255) / 256, 256>>>(ei, E);
    k_agg<<<(N + 7) / 8, 256>>>(out, bias, N);
}

// round 8
// speedup vs baseline: 3.9437x; 1.1076x over previous
#include <cuda_runtime.h>
#include <cuda_fp16.h>
#include <math.h>

#define NNODES 50000
#define NEDGES 1600000
#define INCH   128
#define HEADS  4
#define OUTC   128
#define NEG_SLOPE 0.2f
#define SCAN_B 1024

// Scratch (static device globals; no allocation allowed)
__device__ __half2 g_hb[NNODES * OUTC / 2];   // projected features, fp16x2 [N,64]
__device__ float g_as[NNODES * HEADS];        // a_src [N,4]
__device__ float g_ad[NNODES * HEADS];        // a_dst [N,4]
__device__ int   g_cnt[NNODES];               // in-degree (w/o self loop)
__device__ int   g_off[NNODES];               // CSR offsets (exclusive scan)
__device__ int   g_pos[NEDGES];               // rank of edge within its dst bucket
__device__ int   g_csr_src[NEDGES];           // src node per CSR slot

__device__ __forceinline__ float leaky(float v) {
    return v > 0.0f ? v : NEG_SLOPE * v;
}
__device__ __forceinline__ float4 expleaky4(float4 a, float4 b) {
    float4 r;
    r.x = __expf(leaky(a.x + b.x)); r.y = __expf(leaky(a.y + b.y));
    r.z = __expf(leaky(a.z + b.z)); r.w = __expf(leaky(a.w + b.w));
    return r;
}
__device__ __forceinline__ float sel4(float4 v, int h) {
    return h == 0 ? v.x : h == 1 ? v.y : h == 2 ? v.z : v.w;
}

// packed fp32x2 helpers (FFMA2 only reachable via PTX)
__device__ __forceinline__ unsigned long long pack2(float a, float b) {
    unsigned long long r;
    asm("mov.b64 %0, {%1, %2};" : "=l"(r) : "f"(a), "f"(b));
    return r;
}
__device__ __forceinline__ unsigned long long dup2(float a) {
    unsigned long long r;
    asm("mov.b64 %0, {%1, %1};" : "=l"(r) : "f"(a));
    return r;
}
__device__ __forceinline__ void fma2(unsigned long long& d, unsigned long long a,
                                     unsigned long long b) {
    asm("fma.rn.f32x2 %0, %1, %2, %0;" : "+l"(d) : "l"(a), "l"(b));
}
__device__ __forceinline__ void unpack2(unsigned long long v, float& lo, float& hi) {
    asm("mov.b64 {%0, %1}, %2;" : "=f"(lo), "=f"(hi) : "l"(v));
}

// ---------------------------------------------------------------------------
__global__ void k_zero(int N) {
    int i = blockIdx.x * blockDim.x + threadIdx.x;
    if (i < N) g_cnt[i] = 0;
}

// ---------------------------------------------------------------------------
// Projection + logits + fused degree histogram (capturing per-edge rank).
// Block = 256 threads = 8 warps; each warp computes 8 nodes x 128 cols.
// ---------------------------------------------------------------------------
__global__ void k_proj(const float* __restrict__ x, const float* __restrict__ W,
                       const float* __restrict__ att_s, const float* __restrict__ att_d,
                       const int* __restrict__ ei, int N, int E) {
    __shared__ float xs[64][INCH];  // 32 KB
    int t = threadIdx.x;
    int n0 = blockIdx.x * 64;
    int nvalid = min(64, N - n0);

    for (int i = t * 4; i < 64 * INCH; i += 256 * 4) {
        float4 v = make_float4(0.f, 0.f, 0.f, 0.f);
        if (i < nvalid * INCH) v = *(const float4*)&x[(long long)n0 * INCH + i];
        *(float4*)&xs[0][i] = v;
    }
    __syncthreads();

    int warp = t >> 5;
    int lane = t & 31;
    int nb = warp * 8;

    unsigned long long a01[8], a23[8];
#pragma unroll
    for (int j = 0; j < 8; j++) { a01[j] = 0ull; a23[j] = 0ull; }

#pragma unroll 4
    for (int k = 0; k < INCH; k++) {
        float4 w4 = *(const float4*)&W[k * OUTC + lane * 4];
        unsigned long long w01 = pack2(w4.x, w4.y);
        unsigned long long w23 = pack2(w4.z, w4.w);
#pragma unroll
        for (int j = 0; j < 8; j++) {
            unsigned long long xx = dup2(xs[nb + j][k]);
            fma2(a01[j], w01, xx);
            fma2(a23[j], w23, xx);
        }
    }

    float4 s4 = *(const float4*)&att_s[lane * 4];
    float4 d4 = *(const float4*)&att_d[lane * 4];

#pragma unroll
    for (int j = 0; j < 8; j++) {
        int n = n0 + nb + j;
        float4 acc;
        unpack2(a01[j], acc.x, acc.y);
        unpack2(a23[j], acc.z, acc.w);
        if (n < N) {
            __half2 p0 = __float22half2_rn(make_float2(acc.x, acc.y));
            __half2 p1 = __float22half2_rn(make_float2(acc.z, acc.w));
            uint2 p;
            p.x = *(unsigned int*)&p0;
            p.y = *(unsigned int*)&p1;
            *(uint2*)&g_hb[(long long)n * (OUTC / 2) + lane * 2] = p;
        }

        float vs = acc.x * s4.x + acc.y * s4.y + acc.z * s4.z + acc.w * s4.w;
        float vd = acc.x * d4.x + acc.y * d4.y + acc.z * d4.z + acc.w * d4.w;
#pragma unroll
        for (int o = 4; o > 0; o >>= 1) {
            vs += __shfl_down_sync(0xffffffffu, vs, o);
            vd += __shfl_down_sync(0xffffffffu, vd, o);
        }
        if ((lane & 7) == 0 && n < N) {
            int h = lane >> 3;
            g_as[n * HEADS + h] = vs;
            g_ad[n * HEADS + h] = vd;
        }
    }

    // fused degree histogram; atomic return value = edge's rank in its bucket
    int stride = gridDim.x * 256;
    for (int e = blockIdx.x * 256 + t; e < E; e += stride)
        g_pos[e] = atomicAdd(&g_cnt[ei[E + e]], 1);
}

// ---------------------------------------------------------------------------
// Single-kernel exclusive scan: each block recomputes its base by striding
// over the preceding g_cnt range (<=49k ints), then local prefix.
// ---------------------------------------------------------------------------
__global__ void k_scan(int N) {
    int t = threadIdx.x;
    int b = blockIdx.x;
    __shared__ int sh[256];

    // base = sum g_cnt[0 .. b*SCAN_B)
    int pre = b * SCAN_B;
    if (pre > N) pre = N;
    int part = 0;
    for (int i = t; i < pre; i += 256) part += g_cnt[i];
    sh[t] = part;
    __syncthreads();
#pragma unroll
    for (int o = 128; o > 0; o >>= 1) {
        if (t < o) sh[t] += sh[t + o];
        __syncthreads();
    }
    int base = sh[0];
    __syncthreads();

    // local exclusive prefix over this block's SCAN_B elements
    int i0 = b * SCAN_B + t * 4;
    int v[4];
    int s = 0;
#pragma unroll
    for (int j = 0; j < 4; j++) {
        v[j] = (i0 + j < N) ? g_cnt[i0 + j] : 0;
        s += v[j];
    }
    sh[t] = s;
    __syncthreads();
    for (int o = 1; o < 256; o <<= 1) {
        int u = (t >= o) ? sh[t - o] : 0;
        __syncthreads();
        sh[t] += u;
        __syncthreads();
    }
    int run = base + ((t == 0) ? 0 : sh[t - 1]);
#pragma unroll
    for (int j = 0; j < 4; j++) {
        if (i0 + j < N) g_off[i0 + j] = run;
        run += v[j];
    }
}

// ---------------------------------------------------------------------------
// Atomic-free scatter: slot = off[d] + precomputed rank.
// ---------------------------------------------------------------------------
__global__ void k_scatter(const int* __restrict__ ei, int E) {
    int e = blockIdx.x * blockDim.x + threadIdx.x;
    if (e >= E) return;
    int s = ei[e];
    int d = ei[E + e];
    g_csr_src[g_off[d] + g_pos[e]] = s;
}

// ---------------------------------------------------------------------------
// Fused softmax + weighted aggregate + bias + ELU. WARP per destination node,
// grid-stride over nodes for load balance (each warp sweeps ~3-4 nodes).
// Features gathered as fp16x2 (LDG.64/lane); weights via per-warp smem tile;
// denominator via butterfly reduce. No block syncs, no atomics.
// ---------------------------------------------------------------------------
__global__ void k_agg(float* __restrict__ out, const float* __restrict__ bias, int N) {
    int warp = threadIdx.x >> 5;  // 8 warps/block
    int lane = threadIdx.x & 31;
    int head = lane >> 3;

    __shared__ float s_w[8][32][HEADS];  // 4 KB

    float4 b4 = *(const float4*)&bias[lane * 4];
    int nstride = gridDim.x * 8;

    for (int d = blockIdx.x * 8 + warp; d < N; d += nstride) {
        int start = g_off[d];
        int deg = g_cnt[d];

        float4 ad4 = *(const float4*)&g_ad[d * HEADS];
        float4 asd = *(const float4*)&g_as[d * HEADS];
        float4 wself = expleaky4(asd, ad4);

        // self-loop
        float4 den = (lane == 0) ? wself : make_float4(0.f, 0.f, 0.f, 0.f);
        float wts = sel4(wself, head);
        const __half2* hrow = &g_hb[(long long)d * (OUTC / 2) + lane * 2];
        float2 f0 = __half22float2(hrow[0]);
        float2 f1 = __half22float2(hrow[1]);
        float4 acc;
        acc.x = wts * f0.x; acc.y = wts * f0.y;
        acc.z = wts * f1.x; acc.w = wts * f1.y;

        for (int base = 0; base < deg; base += 32) {
            int m = min(32, deg - base);
            int s = 0;
            float4 w = make_float4(0.f, 0.f, 0.f, 0.f);
            if (lane < m) {
                s = g_csr_src[start + base + lane];
                float4 as4 = *(const float4*)&g_as[s * HEADS];
                w = expleaky4(as4, ad4);
                den.x += w.x; den.y += w.y; den.z += w.z; den.w += w.w;
            }
            *(float4*)&s_w[warp][lane][0] = w;
            __syncwarp();
#pragma unroll 8
            for (int e = 0; e < m; e++) {
                int se = __shfl_sync(0xffffffffu, s, e);
                float wt = s_w[warp][e][head];
                uint2 raw = *(const uint2*)&g_hb[(long long)se * (OUTC / 2) + lane * 2];
                float2 g0 = __half22float2(*(__half2*)&raw.x);
                float2 g1 = __half22float2(*(__half2*)&raw.y);
                acc.x = fmaf(wt, g0.x, acc.x);
                acc.y = fmaf(wt, g0.y, acc.y);
                acc.z = fmaf(wt, g1.x, acc.z);
                acc.w = fmaf(wt, g1.y, acc.w);
            }
            __syncwarp();
        }

        // butterfly reduce denominator
#pragma unroll
        for (int o = 16; o > 0; o >>= 1) {
            den.x += __shfl_xor_sync(0xffffffffu, den.x, o);
            den.y += __shfl_xor_sync(0xffffffffu, den.y, o);
            den.z += __shfl_xor_sync(0xffffffffu, den.z, o);
            den.w += __shfl_xor_sync(0xffffffffu, den.w, o);
        }
        float denv = sel4(den, head) + 1e-16f;

        float4 v;
        v.x = acc.x / denv + b4.x;
        v.y = acc.y / denv + b4.y;
        v.z = acc.z / denv + b4.z;
        v.w = acc.w / denv + b4.w;
        v.x = v.x > 0.f ? v.x : expm1f(v.x);
        v.y = v.y > 0.f ? v.y : expm1f(v.y);
        v.z = v.z > 0.f ? v.z : expm1f(v.z);
        v.w = v.w > 0.f ? v.w : expm1f(v.w);
        *(float4*)&out[(long long)d * OUTC + lane * 4] = v;
    }
}

// ---------------------------------------------------------------------------
extern "C" void kernel_launch(void* const* d_in, const int* in_sizes, int n_in,
                              void* d_out, int out_size) {
    const float* x = (const float*)d_in[0];
    const int* ei = (const int*)d_in[1];   // int32 (jax downcasts int64 w/o x64)
    const float* W = (const float*)d_in[2];
    const float* att_s = (const float*)d_in[3];
    const float* att_d = (const float*)d_in[4];
    const float* bias = (const float*)d_in[5];
    float* out = (float*)d_out;

    int N = in_sizes[0] / INCH;
    int E = in_sizes[1] / 2;
    if (N > NNODES) N = NNODES;
    if (E > NEDGES) E = NEDGES;
    int NB = (N + SCAN_B - 1) / SCAN_B;

    k_zero<<<(N + 255) / 256, 256>>>(N);
    k_proj<<<(N + 63) / 64, 256>>>(x, W, att_s, att_d, ei, N, E);
    k_scan<<<NB, 256>>>(N);
    k_scatter<<<(E + 255) / 256, 256>>>(ei, E);

    int nblk = (N + 7) / 8;
    if (nblk > 2048) nblk = 2048;
    k_agg<<<nblk, 256>>>(out, bias, N);
}